// round 1
// baseline (speedup 1.0000x reference)
#include <cuda_runtime.h>
#include <cstddef>

// Problem constants
constexpr int BB   = 2;
constexpr int SEQ  = 2048;
constexpr int DIMM = 2048;
constexpr int NH   = 32;
constexpr int NKV  = 8;
constexpr int HDIM = 64;

// Scratch (device globals: allocation-free rule)
__device__ float g_q[BB * SEQ * NH * HDIM];       // 32 MB
__device__ float g_k[BB * SEQ * NKV * HDIM];      // 8 MB
__device__ float g_v[BB * SEQ * NKV * HDIM];      // 8 MB
__device__ float g_attn[BB * SEQ * NH * HDIM];    // 32 MB

// ---------------------------------------------------------------------------
// NT SGEMM: C[M,N] = A[M,K] * B[N,K]^T  (A, B row-major with K contiguous)
// 128x128 block tile, BK=16, 256 threads, 8x8 per-thread microtile.
// All dims assumed divisible by tile sizes (true for this problem).
// ---------------------------------------------------------------------------
__global__ __launch_bounds__(256) void gemm_nt(const float* __restrict__ A,
                                               const float* __restrict__ B,
                                               float* __restrict__ C,
                                               int M, int N, int K) {
    __shared__ float As[16][132];
    __shared__ float Bs[16][132];
    const int tid = threadIdx.x;
    const int bm = blockIdx.y * 128;
    const int bn = blockIdx.x * 128;
    const int tx = tid & 15;
    const int ty = tid >> 4;
    const int lr = tid >> 2;          // 0..63
    const int lc = (tid & 3) << 2;    // 0,4,8,12

    float acc[8][8];
#pragma unroll
    for (int i = 0; i < 8; i++)
#pragma unroll
        for (int j = 0; j < 8; j++) acc[i][j] = 0.f;

    for (int k0 = 0; k0 < K; k0 += 16) {
#pragma unroll
        for (int h = 0; h < 2; h++) {
            const int row = lr + h * 64;
            float4 a = *(const float4*)(A + (size_t)(bm + row) * K + k0 + lc);
            As[lc + 0][row] = a.x; As[lc + 1][row] = a.y;
            As[lc + 2][row] = a.z; As[lc + 3][row] = a.w;
            float4 b = *(const float4*)(B + (size_t)(bn + row) * K + k0 + lc);
            Bs[lc + 0][row] = b.x; Bs[lc + 1][row] = b.y;
            Bs[lc + 2][row] = b.z; Bs[lc + 3][row] = b.w;
        }
        __syncthreads();
#pragma unroll
        for (int k = 0; k < 16; k++) {
            float4 a0 = *(const float4*)&As[k][ty * 8];
            float4 a1 = *(const float4*)&As[k][ty * 8 + 4];
            float4 b0 = *(const float4*)&Bs[k][tx * 8];
            float4 b1 = *(const float4*)&Bs[k][tx * 8 + 4];
            float av[8] = {a0.x, a0.y, a0.z, a0.w, a1.x, a1.y, a1.z, a1.w};
            float bv[8] = {b0.x, b0.y, b0.z, b0.w, b1.x, b1.y, b1.z, b1.w};
#pragma unroll
            for (int i = 0; i < 8; i++)
#pragma unroll
                for (int j = 0; j < 8; j++)
                    acc[i][j] = fmaf(av[i], bv[j], acc[i][j]);
        }
        __syncthreads();
    }

#pragma unroll
    for (int i = 0; i < 8; i++) {
        float* crow = C + (size_t)(bm + ty * 8 + i) * N + bn + tx * 8;
        float4 c0 = {acc[i][0], acc[i][1], acc[i][2], acc[i][3]};
        float4 c1 = {acc[i][4], acc[i][5], acc[i][6], acc[i][7]};
        *(float4*)(crow) = c0;
        *(float4*)(crow + 4) = c1;
    }
}

// ---------------------------------------------------------------------------
// RoPE over interleaved (real, imag) pairs.
// t: [B*L, nheads, 64]; freqs: [2, L, 32] (cos then sin).
// One thread per pair.
// ---------------------------------------------------------------------------
__global__ void rope_kernel(float* __restrict__ t, const float* __restrict__ freqs,
                            int nheads, int total) {
    int idx = blockIdx.x * blockDim.x + threadIdx.x;
    if (idx >= total) return;
    int p = idx & 31;           // pair index 0..31
    int rest = idx >> 5;
    int hh = rest % nheads;
    int ml = rest / nheads;     // b*L + l
    int l = ml & (SEQ - 1);
    float c = freqs[l * 32 + p];
    float s = freqs[SEQ * 32 + l * 32 + p];
    float* base = t + ((size_t)ml * nheads + hh) * HDIM + p * 2;
    float t0 = base[0], t1 = base[1];
    base[0] = t0 * c - t1 * s;
    base[1] = t0 * s + t1 * c;
}

// ---------------------------------------------------------------------------
// Causal flash attention with GQA.
// grid: (L/128, H, B), 128 threads. Each thread owns one query row.
// q, acc in registers; K/V tiles (64x64) + S rows (128x65, padded) in dyn smem.
// ---------------------------------------------------------------------------
__global__ __launch_bounds__(128) void flash_attn(const float* __restrict__ Q,
                                                  const float* __restrict__ Kb,
                                                  const float* __restrict__ Vb) {
    extern __shared__ float sm[];
    float* Ks = sm;                  // [64][64]
    float* Vs = sm + 64 * 64;        // [64][64]
    float* Ss = sm + 2 * 64 * 64;    // [128][65]

    const int tid = threadIdx.x;
    const int m0 = blockIdx.x * 128;
    const int h = blockIdx.y;
    const int b = blockIdx.z;
    const int kvh = h >> 2;          // N_REP = 4
    const int i = m0 + tid;

    const float* qrow = Q + ((size_t)(b * SEQ + i) * NH + h) * HDIM;
    float q[HDIM];
#pragma unroll
    for (int d = 0; d < HDIM; d += 4) {
        float4 t4 = *(const float4*)(qrow + d);
        q[d] = t4.x; q[d + 1] = t4.y; q[d + 2] = t4.z; q[d + 3] = t4.w;
    }
    float acc[HDIM];
#pragma unroll
    for (int d = 0; d < HDIM; d++) acc[d] = 0.f;
    float mrow = -1e30f, lrow = 0.f;

    const int nT = m0 / 64 + 2;      // KV tiles covering j <= m0+127
    for (int t = 0; t < nT; t++) {
        const int n0 = t * 64;
        __syncthreads();
        // cooperative K/V tile load (coalesced: consecutive tid -> consecutive float4)
#pragma unroll
        for (int u = 0; u < 8; u++) {
            int e = u * 128 + tid;           // float4 index 0..1023
            int row = e >> 4;
            int col = (e & 15) << 2;
            size_t goff = ((size_t)(b * SEQ + n0 + row) * NKV + kvh) * HDIM + col;
            *(float4*)(Ks + row * 64 + col) = *(const float4*)(Kb + goff);
            *(float4*)(Vs + row * 64 + col) = *(const float4*)(Vb + goff);
        }
        __syncthreads();

        // S = q . K^T (scaled), masked; track row max
        float tmax = -1e30f;
        const bool maybe_mask = (n0 + 63 > i);
        for (int j = 0; j < 64; j++) {
            float s = 0.f;
#pragma unroll
            for (int d = 0; d < HDIM; d += 4) {
                float4 k4 = *(const float4*)(Ks + j * 64 + d);
                s = fmaf(q[d], k4.x, s);
                s = fmaf(q[d + 1], k4.y, s);
                s = fmaf(q[d + 2], k4.z, s);
                s = fmaf(q[d + 3], k4.w, s);
            }
            s *= 0.125f;                      // 1/sqrt(64)
            if (maybe_mask && (n0 + j > i)) s = -1e30f;
            Ss[tid * 65 + j] = s;
            tmax = fmaxf(tmax, s);
        }

        float mnew = fmaxf(mrow, tmax);
        float corr = __expf(mrow - mnew);
        lrow *= corr;
#pragma unroll
        for (int d = 0; d < HDIM; d++) acc[d] *= corr;

        // P = exp(S - mnew); acc += P @ V
        for (int j = 0; j < 64; j++) {
            float p = __expf(Ss[tid * 65 + j] - mnew);
            lrow += p;
#pragma unroll
            for (int d = 0; d < HDIM; d += 4) {
                float4 v4 = *(const float4*)(Vs + j * 64 + d);
                acc[d]     = fmaf(p, v4.x, acc[d]);
                acc[d + 1] = fmaf(p, v4.y, acc[d + 1]);
                acc[d + 2] = fmaf(p, v4.z, acc[d + 2]);
                acc[d + 3] = fmaf(p, v4.w, acc[d + 3]);
            }
        }
        mrow = mnew;
    }

    float inv = 1.f / lrow;
    float* orow = g_attn + ((size_t)(b * SEQ + i) * NH + h) * HDIM;
#pragma unroll
    for (int d = 0; d < HDIM; d += 4) {
        float4 o4 = {acc[d] * inv, acc[d + 1] * inv, acc[d + 2] * inv, acc[d + 3] * inv};
        *(float4*)(orow + d) = o4;
    }
}

// ---------------------------------------------------------------------------
extern "C" void kernel_launch(void* const* d_in, const int* in_sizes, int n_in,
                              void* d_out, int out_size) {
    const float* x     = (const float*)d_in[0];
    const float* freqs = (const float*)d_in[1];
    const float* wq    = (const float*)d_in[2];
    const float* wk    = (const float*)d_in[3];
    const float* wv    = (const float*)d_in[4];
    const float* wo    = (const float*)d_in[5];
    float* out = (float*)d_out;

    float *q, *k, *v, *attn;
    cudaGetSymbolAddress((void**)&q, g_q);
    cudaGetSymbolAddress((void**)&k, g_k);
    cudaGetSymbolAddress((void**)&v, g_v);
    cudaGetSymbolAddress((void**)&attn, g_attn);

    const int smem_bytes = (2 * 64 * 64 + 128 * 65) * (int)sizeof(float); // 66048
    cudaFuncSetAttribute(flash_attn, cudaFuncAttributeMaxDynamicSharedMemorySize,
                         smem_bytes);

    const int M = BB * SEQ;  // 4096

    // Projections
    gemm_nt<<<dim3(DIMM / 128, M / 128), 256>>>(x, wq, q, M, NH * HDIM, DIMM);
    gemm_nt<<<dim3((NKV * HDIM) / 128, M / 128), 256>>>(x, wk, k, M, NKV * HDIM, DIMM);
    gemm_nt<<<dim3((NKV * HDIM) / 128, M / 128), 256>>>(x, wv, v, M, NKV * HDIM, DIMM);

    // RoPE
    {
        int totq = M * NH * (HDIM / 2);
        int totk = M * NKV * (HDIM / 2);
        rope_kernel<<<(totq + 255) / 256, 256>>>(q, freqs, NH, totq);
        rope_kernel<<<(totk + 255) / 256, 256>>>(k, freqs, NKV, totk);
    }

    // Attention
    flash_attn<<<dim3(SEQ / 128, NH, BB), 128, smem_bytes>>>(q, k, v);

    // Output projection
    gemm_nt<<<dim3(DIMM / 128, M / 128), 256>>>(attn, wo, out, M, NH * HDIM, DIMM);
}

// round 3
// speedup vs baseline: 1.3472x; 1.3472x over previous
#include <cuda_runtime.h>
#include <cuda_bf16.h>
#include <cstdint>
#include <cstddef>

// Problem constants
constexpr int BB   = 2;
constexpr int SEQ  = 2048;
constexpr int DIMM = 2048;
constexpr int NH   = 32;
constexpr int NKV  = 8;
constexpr int HDIM = 64;
constexpr int MROWS = BB * SEQ;                    // 4096
constexpr int NQKV  = NH * HDIM + 2 * NKV * HDIM;  // 3072
constexpr int KEFF  = 2 * DIMM;                    // 4096 (hi|lo halves)

// ---------------------------------------------------------------------------
// Scratch (device globals; allocation-free rule)
// ---------------------------------------------------------------------------
__device__ __nv_bfloat16 g_xs[MROWS * KEFF];        // split of x          32 MB
__device__ __nv_bfloat16 g_ws_qkv[NQKV * KEFF];     // split wq|wk|wv      24 MB
__device__ __nv_bfloat16 g_ws_o[DIMM * KEFF];       // split wo            16 MB
__device__ __nv_bfloat16 g_attns[MROWS * KEFF];     // split of attn out   32 MB
__device__ float g_qkv[MROWS * NQKV];               // q|k|v fp32          48 MB
__device__ float g_attn[MROWS * NH * HDIM];         // attn out fp32       32 MB

// ---------------------------------------------------------------------------
// Helpers
// ---------------------------------------------------------------------------
__device__ __forceinline__ uint32_t smem_u32(const void* p) {
    uint32_t a;
    asm("{ .reg .u64 t; cvta.to.shared.u64 t, %1; cvt.u32.u64 %0, t; }" : "=r"(a) : "l"(p));
    return a;
}
__device__ __forceinline__ void cp_async16(uint32_t dst, const void* src) {
    asm volatile("cp.async.cg.shared.global [%0], [%1], 16;" :: "r"(dst), "l"(src));
}
__device__ __forceinline__ void cp_commit() { asm volatile("cp.async.commit_group;" ::: "memory"); }

__device__ __forceinline__ void ldm_x4(uint32_t* r, uint32_t addr) {
    asm volatile("ldmatrix.sync.aligned.m8n8.x4.shared.b16 {%0,%1,%2,%3}, [%4];"
        : "=r"(r[0]), "=r"(r[1]), "=r"(r[2]), "=r"(r[3]) : "r"(addr));
}
__device__ __forceinline__ void mma_16816(float* d, const uint32_t* a, uint32_t b0, uint32_t b1) {
    asm volatile("mma.sync.aligned.m16n8k16.row.col.f32.bf16.bf16.f32 "
        "{%0,%1,%2,%3}, {%4,%5,%6,%7}, {%8,%9}, {%0,%1,%2,%3};"
        : "+f"(d[0]), "+f"(d[1]), "+f"(d[2]), "+f"(d[3])
        : "r"(a[0]), "r"(a[1]), "r"(a[2]), "r"(a[3]), "r"(b0), "r"(b1));
}

// ---------------------------------------------------------------------------
// Split kernel: fp32 [nrows,2048] -> bf16 [row0+nrows, 4096] as [hi|lo]
// ---------------------------------------------------------------------------
__global__ void split_kernel(const float* __restrict__ src, __nv_bfloat16* __restrict__ dst,
                             int row0, int n) {
    int idx = blockIdx.x * blockDim.x + threadIdx.x;   // per float4
    if (idx * 4 >= n) return;
    float4 v = ((const float4*)src)[idx];
    int row = (idx * 4) >> 11;
    int col = (idx * 4) & 2047;
    float a[4] = {v.x, v.y, v.z, v.w};
    union { __nv_bfloat16 b[4]; uint2 u; } H, L;
#pragma unroll
    for (int j = 0; j < 4; j++) {
        __nv_bfloat16 h = __float2bfloat16(a[j]);
        H.b[j] = h;
        L.b[j] = __float2bfloat16(a[j] - __bfloat162float(h));
    }
    size_t base = (size_t)(row0 + row) * KEFF + col;
    *(uint2*)(dst + base) = H.u;
    *(uint2*)(dst + base + 2048) = L.u;
}

// ---------------------------------------------------------------------------
// bf16-split NT GEMM via mma.sync:  C[M,N] = A[M,2048]*B[N,2048]^T (fp32 acc)
// A,B: [rows, 4096] bf16 = [hi|lo].  CTA 128x128, 256 thr (warps 2x4, 64x32),
// K-chunk 32, 3-stage cp.async pipeline, smem row stride 40 elems (80 B).
// grid = (Ntot/128, M/128).
// ---------------------------------------------------------------------------
constexpr int RSTRIDE = 40;                     // elems (80 B)
constexpr int TILE_B  = 128 * RSTRIDE * 2;      // 10240 B per operand tile
constexpr int STAGE_B = 2 * TILE_B;             // 20480 B per stage
constexpr int NCH = 192;                        // 3 segments * 64 chunks of K=32

__global__ __launch_bounds__(256, 1)
void gemm_mma(const __nv_bfloat16* __restrict__ A, const __nv_bfloat16* __restrict__ B,
              float* __restrict__ C, int Ntot) {
    extern __shared__ __align__(128) char dsm[];
    const int tid = threadIdx.x;
    const int wid = tid >> 5;
    const int L = tid & 31;
    const int wm = (wid >> 2) * 64;     // warp M offset in tile
    const int wn = (wid & 3) * 32;      // warp N offset in tile
    const uint32_t dynbase = smem_u32(dsm);

    const int bm = blockIdx.y * 128;
    const int bn = blockIdx.x * 128;
    const __nv_bfloat16* Abase = A + (size_t)bm * KEFF;
    const __nv_bfloat16* Bbase = B + (size_t)bn * KEFF;

    float acc[4][4][4];
#pragma unroll
    for (int i = 0; i < 4; i++)
#pragma unroll
        for (int j = 0; j < 4; j++)
#pragma unroll
            for (int q = 0; q < 4; q++) acc[i][j][q] = 0.f;

    auto load_stage = [&](int s, int c) {
        const int seg = c >> 6;               // 0,1,2
        const int kk = (c & 63) * 32;
        const int aoff = (seg == 2 ? 2048 : 0) + kk;
        const int boff = (seg == 1 ? 2048 : 0) + kk;
        const uint32_t sb = dynbase + s * STAGE_B;
#pragma unroll
        for (int u = 0; u < 2; u++) {         // A: 128 rows x 4 x 16B
            int e = tid + u * 256;
            int row = e >> 2, ch = e & 3;
            cp_async16(sb + row * 80 + ch * 16,
                       Abase + (size_t)row * KEFF + aoff + ch * 8);
        }
#pragma unroll
        for (int u = 0; u < 2; u++) {         // B: 128 rows x 4 x 16B
            int e = tid + u * 256;
            int row = e >> 2, ch = e & 3;
            cp_async16(sb + TILE_B + row * 80 + ch * 16,
                       Bbase + (size_t)row * KEFF + boff + ch * 8);
        }
    };

    load_stage(0, 0); cp_commit();
    load_stage(1, 1); cp_commit();

    const uint32_t lrow = L & 15;
    const uint32_t lcol16 = (L >> 4) * 16;

    for (int i = 0; i < NCH; i++) {
        if (i + 2 < NCH) load_stage((i + 2) % 3, i + 2);
        cp_commit();
        asm volatile("cp.async.wait_group 2;" ::: "memory");
        __syncthreads();

        const uint32_t sb = dynbase + (i % 3) * STAGE_B;
#pragma unroll
        for (int ks = 0; ks < 2; ks++) {
            uint32_t a[4][4], b[2][4];
#pragma unroll
            for (int am = 0; am < 4; am++)
                ldm_x4(a[am], sb + (wm + am * 16 + lrow) * 80 + lcol16 + ks * 32);
#pragma unroll
            for (int g = 0; g < 2; g++)
                ldm_x4(b[g], sb + TILE_B + (wn + g * 16 + lrow) * 80 + lcol16 + ks * 32);
#pragma unroll
            for (int am = 0; am < 4; am++)
#pragma unroll
                for (int an = 0; an < 4; an++)
                    mma_16816(acc[am][an], a[am], b[an >> 1][an & 1], b[an >> 1][2 + (an & 1)]);
        }
        __syncthreads();
    }

    // epilogue: c0,c1 -> (row, col..col+1); c2,c3 -> (row+8, ...)
#pragma unroll
    for (int am = 0; am < 4; am++) {
        int row = bm + wm + am * 16 + (L >> 2);
#pragma unroll
        for (int an = 0; an < 4; an++) {
            int col = bn + wn + an * 8 + (L & 3) * 2;
            float2 lo = make_float2(acc[am][an][0], acc[am][an][1]);
            float2 hi = make_float2(acc[am][an][2], acc[am][an][3]);
            *(float2*)(C + (size_t)row * Ntot + col) = lo;
            *(float2*)(C + (size_t)(row + 8) * Ntot + col) = hi;
        }
    }
}

// ---------------------------------------------------------------------------
// RoPE on g_qkv (row stride NQKV). colbase selects q (0) or k (2048) region.
// ---------------------------------------------------------------------------
__global__ void rope_kernel(float* __restrict__ t, const float* __restrict__ freqs,
                            int nheads, int colbase, int total) {
    int idx = blockIdx.x * blockDim.x + threadIdx.x;
    if (idx >= total) return;
    int p = idx & 31;
    int rest = idx >> 5;
    int hh = rest % nheads;
    int ml = rest / nheads;
    int l = ml & (SEQ - 1);
    float c = freqs[l * 32 + p];
    float s = freqs[SEQ * 32 + l * 32 + p];
    float* base = t + (size_t)ml * NQKV + colbase + hh * HDIM + p * 2;
    float t0 = base[0], t1 = base[1];
    base[0] = t0 * c - t1 * s;
    base[1] = t0 * s + t1 * c;
}

// ---------------------------------------------------------------------------
// Causal flash attention (fp32), reading packed g_qkv.
// grid: (L/128, H, B), 128 threads, one query row per thread.
// ---------------------------------------------------------------------------
__global__ __launch_bounds__(128) void flash_attn(const float* __restrict__ QKV) {
    extern __shared__ float sm[];
    float* Ks = sm;
    float* Vs = sm + 64 * 64;
    float* Ss = sm + 2 * 64 * 64;

    const int tid = threadIdx.x;
    const int m0 = blockIdx.x * 128;
    const int h = blockIdx.y;
    const int b = blockIdx.z;
    const int kvh = h >> 2;
    const int i = m0 + tid;

    const float* qrow = QKV + (size_t)(b * SEQ + i) * NQKV + h * HDIM;
    float q[HDIM];
#pragma unroll
    for (int d = 0; d < HDIM; d += 4) {
        float4 t4 = *(const float4*)(qrow + d);
        q[d] = t4.x; q[d + 1] = t4.y; q[d + 2] = t4.z; q[d + 3] = t4.w;
    }
    float acc[HDIM];
#pragma unroll
    for (int d = 0; d < HDIM; d++) acc[d] = 0.f;
    float mrow = -1e30f, lrow = 0.f;

    const int kcol = 2048 + kvh * HDIM;
    const int vcol = 2560 + kvh * HDIM;

    const int nT = m0 / 64 + 2;
    for (int t = 0; t < nT; t++) {
        const int n0 = t * 64;
        __syncthreads();
#pragma unroll
        for (int u = 0; u < 8; u++) {
            int e = u * 128 + tid;
            int row = e >> 4;
            int col = (e & 15) << 2;
            size_t roff = (size_t)(b * SEQ + n0 + row) * NQKV;
            *(float4*)(Ks + row * 64 + col) = *(const float4*)(QKV + roff + kcol + col);
            *(float4*)(Vs + row * 64 + col) = *(const float4*)(QKV + roff + vcol + col);
        }
        __syncthreads();

        float tmax = -1e30f;
        const bool maybe_mask = (n0 + 63 > i);
        for (int j = 0; j < 64; j++) {
            float s = 0.f;
#pragma unroll
            for (int d = 0; d < HDIM; d += 4) {
                float4 k4 = *(const float4*)(Ks + j * 64 + d);
                s = fmaf(q[d], k4.x, s);
                s = fmaf(q[d + 1], k4.y, s);
                s = fmaf(q[d + 2], k4.z, s);
                s = fmaf(q[d + 3], k4.w, s);
            }
            s *= 0.125f;
            if (maybe_mask && (n0 + j > i)) s = -1e30f;
            Ss[tid * 65 + j] = s;
            tmax = fmaxf(tmax, s);
        }

        float mnew = fmaxf(mrow, tmax);
        float corr = __expf(mrow - mnew);
        lrow *= corr;
#pragma unroll
        for (int d = 0; d < HDIM; d++) acc[d] *= corr;

        for (int j = 0; j < 64; j++) {
            float p = __expf(Ss[tid * 65 + j] - mnew);
            lrow += p;
#pragma unroll
            for (int d = 0; d < HDIM; d += 4) {
                float4 v4 = *(const float4*)(Vs + j * 64 + d);
                acc[d]     = fmaf(p, v4.x, acc[d]);
                acc[d + 1] = fmaf(p, v4.y, acc[d + 1]);
                acc[d + 2] = fmaf(p, v4.z, acc[d + 2]);
                acc[d + 3] = fmaf(p, v4.w, acc[d + 3]);
            }
        }
        mrow = mnew;
    }

    float inv = 1.f / lrow;
    float* orow = g_attn + ((size_t)(b * SEQ + i) * NH + h) * HDIM;
#pragma unroll
    for (int d = 0; d < HDIM; d += 4) {
        float4 o4 = {acc[d] * inv, acc[d + 1] * inv, acc[d + 2] * inv, acc[d + 3] * inv};
        *(float4*)(orow + d) = o4;
    }
}

// ---------------------------------------------------------------------------
extern "C" void kernel_launch(void* const* d_in, const int* in_sizes, int n_in,
                              void* d_out, int out_size) {
    const float* x     = (const float*)d_in[0];
    const float* freqs = (const float*)d_in[1];
    const float* wq    = (const float*)d_in[2];
    const float* wk    = (const float*)d_in[3];
    const float* wv    = (const float*)d_in[4];
    const float* wo    = (const float*)d_in[5];
    float* out = (float*)d_out;

    __nv_bfloat16 *xs, *wsqkv, *wso, *attns;
    float *qkv, *attn;
    cudaGetSymbolAddress((void**)&xs, g_xs);
    cudaGetSymbolAddress((void**)&wsqkv, g_ws_qkv);
    cudaGetSymbolAddress((void**)&wso, g_ws_o);
    cudaGetSymbolAddress((void**)&attns, g_attns);
    cudaGetSymbolAddress((void**)&qkv, g_qkv);
    cudaGetSymbolAddress((void**)&attn, g_attn);

    const int gemm_smem = 3 * STAGE_B;                       // 61440
    const int fa_smem = (2 * 64 * 64 + 128 * 65) * (int)sizeof(float);
    static bool attr_done = false;
    if (!attr_done) {
        cudaFuncSetAttribute(gemm_mma, cudaFuncAttributeMaxDynamicSharedMemorySize, gemm_smem);
        cudaFuncSetAttribute(flash_attn, cudaFuncAttributeMaxDynamicSharedMemorySize, fa_smem);
        attr_done = true;
    }

    // 1) splits
    {
        int n = MROWS * DIMM;
        split_kernel<<<(n / 4 + 255) / 256, 256>>>(x, xs, 0, n);
        n = 2048 * DIMM;
        split_kernel<<<(n / 4 + 255) / 256, 256>>>(wq, wsqkv, 0, n);
        n = 512 * DIMM;
        split_kernel<<<(n / 4 + 255) / 256, 256>>>(wk, wsqkv, 2048, n);
        split_kernel<<<(n / 4 + 255) / 256, 256>>>(wv, wsqkv, 2560, n);
        n = 2048 * DIMM;
        split_kernel<<<(n / 4 + 255) / 256, 256>>>(wo, wso, 0, n);
    }

    // 2) fused QKV projection: [4096,3072] = xs * wsqkv^T
    gemm_mma<<<dim3(NQKV / 128, MROWS / 128), 256, gemm_smem>>>(xs, wsqkv, qkv, NQKV);

    // 3) RoPE
    {
        int totq = MROWS * NH * 32;
        int totk = MROWS * NKV * 32;
        rope_kernel<<<(totq + 255) / 256, 256>>>(qkv, freqs, NH, 0, totq);
        rope_kernel<<<(totk + 255) / 256, 256>>>(qkv, freqs, NKV, 2048, totk);
    }

    // 4) attention
    flash_attn<<<dim3(SEQ / 128, NH, BB), 128, fa_smem>>>(qkv);

    // 5) split attn output, 6) O projection
    {
        int n = MROWS * DIMM;
        split_kernel<<<(n / 4 + 255) / 256, 256>>>(attn, attns, 0, n);
    }
    gemm_mma<<<dim3(DIMM / 128, MROWS / 128), 256, gemm_smem>>>(attns, wso, out, DIMM);
}

// round 4
// speedup vs baseline: 2.5725x; 1.9095x over previous
#include <cuda_runtime.h>
#include <cuda_bf16.h>
#include <cstdint>
#include <cstddef>

// Problem constants
constexpr int BB   = 2;
constexpr int SEQ  = 2048;
constexpr int DIMM = 2048;
constexpr int NH   = 32;
constexpr int NKV  = 8;
constexpr int HDIM = 64;
constexpr int MROWS = BB * SEQ;                    // 4096
constexpr int NQKV  = NH * HDIM + 2 * NKV * HDIM;  // 3072
constexpr int KEFF  = 2 * DIMM;                    // 4096 (hi|lo halves)

// ---------------------------------------------------------------------------
// Scratch (device globals; allocation-free rule)
// ---------------------------------------------------------------------------
__device__ __nv_bfloat16 g_xs[MROWS * KEFF];        // split of x          32 MB
__device__ __nv_bfloat16 g_ws_qkv[NQKV * KEFF];     // split wq|wk|wv      24 MB
__device__ __nv_bfloat16 g_ws_o[DIMM * KEFF];       // split wo            16 MB
__device__ __nv_bfloat16 g_attns[MROWS * KEFF];     // split of attn out   32 MB
__device__ float g_qkv[MROWS * NQKV];               // q|k|v fp32          48 MB
__device__ float g_attn[MROWS * NH * HDIM];         // attn out fp32       32 MB
// attention inputs, bf16 [hi(64) | lo(64)] per row
__device__ __nv_bfloat16 g_qs[BB * NH * SEQ * 128];   // 32 MB (q prescaled by 1/8)
__device__ __nv_bfloat16 g_ks[BB * NKV * SEQ * 128];  // 8 MB
__device__ __nv_bfloat16 g_vs[BB * NKV * SEQ * 128];  // 8 MB

// ---------------------------------------------------------------------------
// Helpers
// ---------------------------------------------------------------------------
__device__ __forceinline__ uint32_t smem_u32(const void* p) {
    uint32_t a;
    asm("{ .reg .u64 t; cvta.to.shared.u64 t, %1; cvt.u32.u64 %0, t; }" : "=r"(a) : "l"(p));
    return a;
}
__device__ __forceinline__ void cp_async16(uint32_t dst, const void* src) {
    asm volatile("cp.async.cg.shared.global [%0], [%1], 16;" :: "r"(dst), "l"(src));
}
__device__ __forceinline__ void cp_commit() { asm volatile("cp.async.commit_group;" ::: "memory"); }

__device__ __forceinline__ void ldm_x4(uint32_t* r, uint32_t addr) {
    asm volatile("ldmatrix.sync.aligned.m8n8.x4.shared.b16 {%0,%1,%2,%3}, [%4];"
        : "=r"(r[0]), "=r"(r[1]), "=r"(r[2]), "=r"(r[3]) : "r"(addr));
}
__device__ __forceinline__ void ldm_x4_t(uint32_t* r, uint32_t addr) {
    asm volatile("ldmatrix.sync.aligned.m8n8.x4.trans.shared.b16 {%0,%1,%2,%3}, [%4];"
        : "=r"(r[0]), "=r"(r[1]), "=r"(r[2]), "=r"(r[3]) : "r"(addr));
}
__device__ __forceinline__ void mma_16816(float* d, const uint32_t* a, uint32_t b0, uint32_t b1) {
    asm volatile("mma.sync.aligned.m16n8k16.row.col.f32.bf16.bf16.f32 "
        "{%0,%1,%2,%3}, {%4,%5,%6,%7}, {%8,%9}, {%0,%1,%2,%3};"
        : "+f"(d[0]), "+f"(d[1]), "+f"(d[2]), "+f"(d[3])
        : "r"(a[0]), "r"(a[1]), "r"(a[2]), "r"(a[3]), "r"(b0), "r"(b1));
}
__device__ __forceinline__ float ex2f(float x) {
    float r;
    asm("ex2.approx.f32 %0, %1;" : "=f"(r) : "f"(x));
    return r;
}
// pack bf16 hi-halves of two fp32: result = {lo16: hi(a), hi16: hi(b)}
__device__ __forceinline__ uint32_t prmt_hi(float a, float b) {
    uint32_t r;
    asm("prmt.b32 %0, %1, %2, 0x7632;" : "=r"(r) : "r"(__float_as_uint(a)), "r"(__float_as_uint(b)));
    return r;
}
__device__ __forceinline__ uint32_t pack_bf16(float lo, float hi) {
    uint32_t r;
    asm("cvt.rn.bf16x2.f32 %0, %2, %1;" : "=r"(r) : "f"(lo), "f"(hi));
    return r;
}
__device__ __forceinline__ float trunc_bf(float x) {
    return __uint_as_float(__float_as_uint(x) & 0xffff0000u);
}

// ---------------------------------------------------------------------------
// Split kernel: fp32 [nrows,2048] -> bf16 [row0+nrows, 4096] as [hi|lo]
// ---------------------------------------------------------------------------
__global__ void split_kernel(const float* __restrict__ src, __nv_bfloat16* __restrict__ dst,
                             int row0, int n) {
    int idx = blockIdx.x * blockDim.x + threadIdx.x;
    if (idx * 4 >= n) return;
    float4 v = ((const float4*)src)[idx];
    int row = (idx * 4) >> 11;
    int col = (idx * 4) & 2047;
    float a[4] = {v.x, v.y, v.z, v.w};
    union { __nv_bfloat16 b[4]; uint2 u; } H, L;
#pragma unroll
    for (int j = 0; j < 4; j++) {
        __nv_bfloat16 h = __float2bfloat16(a[j]);
        H.b[j] = h;
        L.b[j] = __float2bfloat16(a[j] - __bfloat162float(h));
    }
    size_t base = (size_t)(row0 + row) * KEFF + col;
    *(uint2*)(dst + base) = H.u;
    *(uint2*)(dst + base + 2048) = L.u;
}

// ---------------------------------------------------------------------------
// bf16-split NT GEMM via mma.sync (same as R3)
// ---------------------------------------------------------------------------
constexpr int RSTRIDE = 40;
constexpr int TILE_B  = 128 * RSTRIDE * 2;
constexpr int STAGE_B = 2 * TILE_B;
constexpr int NCH = 192;

__global__ __launch_bounds__(256, 1)
void gemm_mma(const __nv_bfloat16* __restrict__ A, const __nv_bfloat16* __restrict__ B,
              float* __restrict__ C, int Ntot) {
    extern __shared__ __align__(128) char dsm[];
    const int tid = threadIdx.x;
    const int wid = tid >> 5;
    const int L = tid & 31;
    const int wm = (wid >> 2) * 64;
    const int wn = (wid & 3) * 32;
    const uint32_t dynbase = smem_u32(dsm);

    const int bm = blockIdx.y * 128;
    const int bn = blockIdx.x * 128;
    const __nv_bfloat16* Abase = A + (size_t)bm * KEFF;
    const __nv_bfloat16* Bbase = B + (size_t)bn * KEFF;

    float acc[4][4][4];
#pragma unroll
    for (int i = 0; i < 4; i++)
#pragma unroll
        for (int j = 0; j < 4; j++)
#pragma unroll
            for (int q = 0; q < 4; q++) acc[i][j][q] = 0.f;

    auto load_stage = [&](int s, int c) {
        const int seg = c >> 6;
        const int kk = (c & 63) * 32;
        const int aoff = (seg == 2 ? 2048 : 0) + kk;
        const int boff = (seg == 1 ? 2048 : 0) + kk;
        const uint32_t sb = dynbase + s * STAGE_B;
#pragma unroll
        for (int u = 0; u < 2; u++) {
            int e = tid + u * 256;
            int row = e >> 2, ch = e & 3;
            cp_async16(sb + row * 80 + ch * 16,
                       Abase + (size_t)row * KEFF + aoff + ch * 8);
        }
#pragma unroll
        for (int u = 0; u < 2; u++) {
            int e = tid + u * 256;
            int row = e >> 2, ch = e & 3;
            cp_async16(sb + TILE_B + row * 80 + ch * 16,
                       Bbase + (size_t)row * KEFF + boff + ch * 8);
        }
    };

    load_stage(0, 0); cp_commit();
    load_stage(1, 1); cp_commit();

    const uint32_t lrow = L & 15;
    const uint32_t lcol16 = (L >> 4) * 16;

    for (int i = 0; i < NCH; i++) {
        if (i + 2 < NCH) load_stage((i + 2) % 3, i + 2);
        cp_commit();
        asm volatile("cp.async.wait_group 2;" ::: "memory");
        __syncthreads();

        const uint32_t sb = dynbase + (i % 3) * STAGE_B;
#pragma unroll
        for (int ks = 0; ks < 2; ks++) {
            uint32_t a[4][4], b[2][4];
#pragma unroll
            for (int am = 0; am < 4; am++)
                ldm_x4(a[am], sb + (wm + am * 16 + lrow) * 80 + lcol16 + ks * 32);
#pragma unroll
            for (int g = 0; g < 2; g++)
                ldm_x4(b[g], sb + TILE_B + (wn + g * 16 + lrow) * 80 + lcol16 + ks * 32);
#pragma unroll
            for (int am = 0; am < 4; am++)
#pragma unroll
                for (int an = 0; an < 4; an++)
                    mma_16816(acc[am][an], a[am], b[an >> 1][an & 1], b[an >> 1][2 + (an & 1)]);
        }
        __syncthreads();
    }

#pragma unroll
    for (int am = 0; am < 4; am++) {
        int row = bm + wm + am * 16 + (L >> 2);
#pragma unroll
        for (int an = 0; an < 4; an++) {
            int col = bn + wn + an * 8 + (L & 3) * 2;
            float2 lo = make_float2(acc[am][an][0], acc[am][an][1]);
            float2 hi = make_float2(acc[am][an][2], acc[am][an][3]);
            *(float2*)(C + (size_t)row * Ntot + col) = lo;
            *(float2*)(C + (size_t)(row + 8) * Ntot + col) = hi;
        }
    }
}

// ---------------------------------------------------------------------------
// Fused RoPE + hi/lo split for attention inputs.
// Reads g_qkv [4096][3072]; writes g_qs (q*0.125, roped), g_ks (roped), g_vs.
// grid = MROWS blocks, 256 threads; 1536 pair-units per row.
// ---------------------------------------------------------------------------
__global__ __launch_bounds__(256) void rope_split(const float* __restrict__ qkv,
                                                  const float* __restrict__ freqs) {
    const int ml = blockIdx.x;            // b*SEQ + l
    const int l = ml & (SEQ - 1);
    const int b = ml >> 11;
    const float* row = qkv + (size_t)ml * NQKV;

#pragma unroll
    for (int it = 0; it < 6; it++) {
        int u = threadIdx.x + it * 256;
        float v0, v1;
        __nv_bfloat16* dst;
        if (u < 1024) {                   // q: h = u>>5, pair p = u&31
            int h = u >> 5, p = u & 31;
            float2 t = *(const float2*)(row + h * 64 + 2 * p);
            float c = freqs[l * 32 + p];
            float s = freqs[SEQ * 32 + l * 32 + p];
            v0 = (t.x * c - t.y * s) * 0.125f;
            v1 = (t.x * s + t.y * c) * 0.125f;
            dst = g_qs + ((size_t)(b * NH + h) * SEQ + l) * 128 + 2 * p;
        } else if (u < 1280) {            // k
            int u2 = u - 1024;
            int kh = u2 >> 5, p = u2 & 31;
            float2 t = *(const float2*)(row + 2048 + kh * 64 + 2 * p);
            float c = freqs[l * 32 + p];
            float s = freqs[SEQ * 32 + l * 32 + p];
            v0 = t.x * c - t.y * s;
            v1 = t.x * s + t.y * c;
            dst = g_ks + ((size_t)(b * NKV + kh) * SEQ + l) * 128 + 2 * p;
        } else {                          // v
            int u2 = u - 1280;
            int kh = u2 >> 5, p = u2 & 31;
            float2 t = *(const float2*)(row + 2560 + kh * 64 + 2 * p);
            v0 = t.x; v1 = t.y;
            dst = g_vs + ((size_t)(b * NKV + kh) * SEQ + l) * 128 + 2 * p;
        }
        __nv_bfloat16 h0 = __float2bfloat16(v0);
        __nv_bfloat16 h1 = __float2bfloat16(v1);
        dst[0] = h0;
        dst[1] = h1;
        dst[64] = __float2bfloat16(v0 - __bfloat162float(h0));
        dst[65] = __float2bfloat16(v1 - __bfloat162float(h1));
    }
}

// ---------------------------------------------------------------------------
// Tensor-core causal flash attention, bf16 hi/lo splits both sides.
// grid: (SEQ/64, NH, BB); 128 threads (4 warps x 16 rows).
// smem: Qh Ql Kh Kl Vh Vl, each 64 rows x 144B stride = 9216B -> 55296B.
// ---------------------------------------------------------------------------
constexpr int AT_STR = 144;                        // bytes per smem row
constexpr int AT_ARR = 64 * AT_STR;                // 9216
constexpr int AT_SMEM = 6 * AT_ARR;                // 55296
constexpr float LOG2E = 1.4426950408889634f;

__global__ __launch_bounds__(128, 2)
void flash_attn_mma(const __nv_bfloat16* __restrict__ Qs,
                    const __nv_bfloat16* __restrict__ Ks,
                    const __nv_bfloat16* __restrict__ Vs) {
    extern __shared__ __align__(128) char fsm[];
    const uint32_t sQh = smem_u32(fsm);
    const uint32_t sQl = sQh + AT_ARR;
    const uint32_t sKh = sQh + 2 * AT_ARR;
    const uint32_t sKl = sQh + 3 * AT_ARR;
    const uint32_t sVh = sQh + 4 * AT_ARR;
    const uint32_t sVl = sQh + 5 * AT_ARR;

    const int tid = threadIdx.x;
    const int wid = tid >> 5;
    const int L = tid & 31;
    const int wm = wid * 16;
    const uint32_t lrow = L & 15;
    const uint32_t lcol16 = (L >> 4) * 16;

    const int m0 = blockIdx.x * 64;
    const int h = blockIdx.y;
    const int b = blockIdx.z;
    const int kvh = h >> 2;

    // ---- load Q tile (hi|lo) ----
    const __nv_bfloat16* qsrc = Qs + ((size_t)(b * NH + h) * SEQ + m0) * 128;
#pragma unroll
    for (int u = 0; u < 8; u++) {
        int e = tid + u * 128;
        int row = e >> 4, ch = e & 15;
        uint32_t dst = (ch < 8) ? (sQh + row * AT_STR + ch * 16)
                                : (sQl + row * AT_STR + (ch - 8) * 16);
        cp_async16(dst, qsrc + (size_t)row * 128 + ch * 8);
    }
    cp_commit();
    asm volatile("cp.async.wait_group 0;" ::: "memory");
    __syncthreads();

    uint32_t qh[4][4], ql[4][4];
#pragma unroll
    for (int kg = 0; kg < 4; kg++) {
        ldm_x4(qh[kg], sQh + (wm + lrow) * AT_STR + kg * 32 + lcol16);
        ldm_x4(ql[kg], sQl + (wm + lrow) * AT_STR + kg * 32 + lcol16);
    }

    float O[8][4];
#pragma unroll
    for (int i = 0; i < 8; i++)
#pragma unroll
        for (int j = 0; j < 4; j++) O[i][j] = 0.f;
    float mr0 = -1e30f, mr1 = -1e30f, lr0 = 0.f, lr1 = 0.f;

    const __nv_bfloat16* ksrc = Ks + ((size_t)(b * NKV + kvh) * SEQ) * 128;
    const __nv_bfloat16* vsrc = Vs + ((size_t)(b * NKV + kvh) * SEQ) * 128;

    const int nT = m0 / 64 + 1;
    for (int t = 0; t < nT; t++) {
        const int n0 = t * 64;
        __syncthreads();
#pragma unroll
        for (int u = 0; u < 8; u++) {
            int e = tid + u * 128;
            int row = e >> 4, ch = e & 15;
            uint32_t kd = (ch < 8) ? (sKh + row * AT_STR + ch * 16)
                                   : (sKl + row * AT_STR + (ch - 8) * 16);
            uint32_t vd = (ch < 8) ? (sVh + row * AT_STR + ch * 16)
                                   : (sVl + row * AT_STR + (ch - 8) * 16);
            cp_async16(kd, ksrc + (size_t)(n0 + row) * 128 + ch * 8);
            cp_async16(vd, vsrc + (size_t)(n0 + row) * 128 + ch * 8);
        }
        cp_commit();
        asm volatile("cp.async.wait_group 0;" ::: "memory");
        __syncthreads();

        // ---- S = Q K^T (3 split passes) ----
        float S[8][4];
#pragma unroll
        for (int i = 0; i < 8; i++)
#pragma unroll
            for (int j = 0; j < 4; j++) S[i][j] = 0.f;

#pragma unroll
        for (int kg = 0; kg < 4; kg++) {
            uint32_t kfh[4][4], kfl[4][4];
#pragma unroll
            for (int nn = 0; nn < 4; nn++) {
                ldm_x4(kfh[nn], sKh + (nn * 16 + lrow) * AT_STR + kg * 32 + lcol16);
                ldm_x4(kfl[nn], sKl + (nn * 16 + lrow) * AT_STR + kg * 32 + lcol16);
            }
#pragma unroll
            for (int ng = 0; ng < 8; ng++) {
                int nn = ng >> 1, e = ng & 1;
                mma_16816(S[ng], qh[kg], kfh[nn][e], kfh[nn][2 + e]);
                mma_16816(S[ng], qh[kg], kfl[nn][e], kfl[nn][2 + e]);
                mma_16816(S[ng], ql[kg], kfh[nn][e], kfh[nn][2 + e]);
            }
        }

        // ---- mask (diagonal tile) ----
        const int r0 = wm + (L >> 2);
        const int r1 = r0 + 8;
        if (t == nT - 1) {
#pragma unroll
            for (int ng = 0; ng < 8; ng++) {
                int c0 = ng * 8 + (L & 3) * 2;
                if (c0 > r0)     S[ng][0] = -1e30f;
                if (c0 + 1 > r0) S[ng][1] = -1e30f;
                if (c0 > r1)     S[ng][2] = -1e30f;
                if (c0 + 1 > r1) S[ng][3] = -1e30f;
            }
        }

        // ---- online softmax ----
        float t0 = -1e30f, t1 = -1e30f;
#pragma unroll
        for (int ng = 0; ng < 8; ng++) {
            t0 = fmaxf(t0, fmaxf(S[ng][0], S[ng][1]));
            t1 = fmaxf(t1, fmaxf(S[ng][2], S[ng][3]));
        }
        t0 = fmaxf(t0, __shfl_xor_sync(0xffffffffu, t0, 1));
        t0 = fmaxf(t0, __shfl_xor_sync(0xffffffffu, t0, 2));
        t1 = fmaxf(t1, __shfl_xor_sync(0xffffffffu, t1, 1));
        t1 = fmaxf(t1, __shfl_xor_sync(0xffffffffu, t1, 2));

        float mn0 = fmaxf(mr0, t0), mn1 = fmaxf(mr1, t1);
        float corr0 = ex2f((mr0 - mn0) * LOG2E);
        float corr1 = ex2f((mr1 - mn1) * LOG2E);
        lr0 *= corr0; lr1 *= corr1;
#pragma unroll
        for (int ng = 0; ng < 8; ng++) {
            O[ng][0] *= corr0; O[ng][1] *= corr0;
            O[ng][2] *= corr1; O[ng][3] *= corr1;
        }
        mr0 = mn0; mr1 = mn1;
        const float mb0 = mn0 * LOG2E, mb1 = mn1 * LOG2E;

        uint32_t pah[4][4], pal[4][4];
        float s0 = 0.f, s1 = 0.f;
#pragma unroll
        for (int kg = 0; kg < 4; kg++) {
            float p[8];
#pragma unroll
            for (int e = 0; e < 2; e++) {
                const int g = 2 * kg + e;
                p[4 * e + 0] = ex2f(fmaf(S[g][0], LOG2E, -mb0));
                p[4 * e + 1] = ex2f(fmaf(S[g][1], LOG2E, -mb0));
                p[4 * e + 2] = ex2f(fmaf(S[g][2], LOG2E, -mb1));
                p[4 * e + 3] = ex2f(fmaf(S[g][3], LOG2E, -mb1));
                s0 += p[4 * e] + p[4 * e + 1];
                s1 += p[4 * e + 2] + p[4 * e + 3];
            }
            pah[kg][0] = prmt_hi(p[0], p[1]);
            pah[kg][1] = prmt_hi(p[2], p[3]);
            pah[kg][2] = prmt_hi(p[4], p[5]);
            pah[kg][3] = prmt_hi(p[6], p[7]);
            pal[kg][0] = pack_bf16(p[0] - trunc_bf(p[0]), p[1] - trunc_bf(p[1]));
            pal[kg][1] = pack_bf16(p[2] - trunc_bf(p[2]), p[3] - trunc_bf(p[3]));
            pal[kg][2] = pack_bf16(p[4] - trunc_bf(p[4]), p[5] - trunc_bf(p[5]));
            pal[kg][3] = pack_bf16(p[6] - trunc_bf(p[6]), p[7] - trunc_bf(p[7]));
        }
        s0 += __shfl_xor_sync(0xffffffffu, s0, 1);
        s0 += __shfl_xor_sync(0xffffffffu, s0, 2);
        s1 += __shfl_xor_sync(0xffffffffu, s1, 1);
        s1 += __shfl_xor_sync(0xffffffffu, s1, 2);
        lr0 += s0; lr1 += s1;

        // ---- O += P V (3 split passes) ----
#pragma unroll
        for (int kg = 0; kg < 4; kg++) {
            uint32_t vfh[4][4], vfl[4][4];
#pragma unroll
            for (int cp = 0; cp < 4; cp++) {
                ldm_x4_t(vfh[cp], sVh + (kg * 16 + lrow) * AT_STR + cp * 32 + lcol16);
                ldm_x4_t(vfl[cp], sVl + (kg * 16 + lrow) * AT_STR + cp * 32 + lcol16);
            }
#pragma unroll
            for (int cp = 0; cp < 4; cp++) {
#pragma unroll
                for (int e = 0; e < 2; e++) {
                    const int ng = 2 * cp + e;
                    mma_16816(O[ng], pah[kg], vfh[cp][2 * e], vfh[cp][2 * e + 1]);
                    mma_16816(O[ng], pah[kg], vfl[cp][2 * e], vfl[cp][2 * e + 1]);
                    mma_16816(O[ng], pal[kg], vfh[cp][2 * e], vfh[cp][2 * e + 1]);
                }
            }
        }
    }

    // ---- write out ----
    const float inv0 = 1.f / lr0;
    const float inv1 = 1.f / lr1;
    const int r0 = wm + (L >> 2);
    float* o0 = g_attn + (size_t)((b * SEQ + m0 + r0)) * 2048 + h * 64 + (L & 3) * 2;
    float* o1 = g_attn + (size_t)((b * SEQ + m0 + r0 + 8)) * 2048 + h * 64 + (L & 3) * 2;
#pragma unroll
    for (int ng = 0; ng < 8; ng++) {
        *(float2*)(o0 + ng * 8) = make_float2(O[ng][0] * inv0, O[ng][1] * inv0);
        *(float2*)(o1 + ng * 8) = make_float2(O[ng][2] * inv1, O[ng][3] * inv1);
    }
}

// ---------------------------------------------------------------------------
extern "C" void kernel_launch(void* const* d_in, const int* in_sizes, int n_in,
                              void* d_out, int out_size) {
    const float* x     = (const float*)d_in[0];
    const float* freqs = (const float*)d_in[1];
    const float* wq    = (const float*)d_in[2];
    const float* wk    = (const float*)d_in[3];
    const float* wv    = (const float*)d_in[4];
    const float* wo    = (const float*)d_in[5];
    float* out = (float*)d_out;

    __nv_bfloat16 *xs, *wsqkv, *wso, *attns, *qs, *ks, *vs;
    float *qkv, *attn;
    cudaGetSymbolAddress((void**)&xs, g_xs);
    cudaGetSymbolAddress((void**)&wsqkv, g_ws_qkv);
    cudaGetSymbolAddress((void**)&wso, g_ws_o);
    cudaGetSymbolAddress((void**)&attns, g_attns);
    cudaGetSymbolAddress((void**)&qkv, g_qkv);
    cudaGetSymbolAddress((void**)&attn, g_attn);
    cudaGetSymbolAddress((void**)&qs, g_qs);
    cudaGetSymbolAddress((void**)&ks, g_ks);
    cudaGetSymbolAddress((void**)&vs, g_vs);

    const int gemm_smem = 3 * STAGE_B;
    static bool attr_done = false;
    if (!attr_done) {
        cudaFuncSetAttribute(gemm_mma, cudaFuncAttributeMaxDynamicSharedMemorySize, gemm_smem);
        cudaFuncSetAttribute(flash_attn_mma, cudaFuncAttributeMaxDynamicSharedMemorySize, AT_SMEM);
        attr_done = true;
    }

    // 1) splits of x + weights
    {
        int n = MROWS * DIMM;
        split_kernel<<<(n / 4 + 255) / 256, 256>>>(x, xs, 0, n);
        n = 2048 * DIMM;
        split_kernel<<<(n / 4 + 255) / 256, 256>>>(wq, wsqkv, 0, n);
        n = 512 * DIMM;
        split_kernel<<<(n / 4 + 255) / 256, 256>>>(wk, wsqkv, 2048, n);
        split_kernel<<<(n / 4 + 255) / 256, 256>>>(wv, wsqkv, 2560, n);
        n = 2048 * DIMM;
        split_kernel<<<(n / 4 + 255) / 256, 256>>>(wo, wso, 0, n);
    }

    // 2) fused QKV projection
    gemm_mma<<<dim3(NQKV / 128, MROWS / 128), 256, gemm_smem>>>(xs, wsqkv, qkv, NQKV);

    // 3) RoPE + split attention inputs
    rope_split<<<MROWS, 256>>>(qkv, freqs);

    // 4) tensor-core attention
    flash_attn_mma<<<dim3(SEQ / 64, NH, BB), 128, AT_SMEM>>>(qs, ks, vs);

    // 5) split attn output, 6) O projection
    {
        int n = MROWS * DIMM;
        split_kernel<<<(n / 4 + 255) / 256, 256>>>(attn, attns, 0, n);
    }
    gemm_mma<<<dim3(DIMM / 128, MROWS / 128), 256, gemm_smem>>>(attns, wso, out, DIMM);
}